// round 1
// baseline (speedup 1.0000x reference)
#include <cuda_runtime.h>
#include <cuda_bf16.h>

#define N 8192
#define NBLOCKS 256
#define NTHREADS 256
#define I_PER_BLOCK 32          // i's per block (one per lane)
#define JSPLIT 8                // warps per block partition the j range
#define JCHUNK (N / JSPLIT)     // 1024 j's per thread

__device__ float g_partials[NBLOCKS];

// Each block: 32 i's (lanes), 8 warps split j-range. Full (time, exph) table
// lives in shared as interleaved float2 -> one broadcast LDS.64 per j.
__global__ void __launch_bounds__(NTHREADS, 1)
cox_risk_kernel(const float* __restrict__ hazard,
                const float* __restrict__ time,
                const float* __restrict__ censor)
{
    extern __shared__ float2 te[];   // te[j] = (time[j], exp(hazard[j]))  : 64 KB
    const int tid = threadIdx.x;

    // Cooperative fill of the full table
    for (int j = tid; j < N; j += NTHREADS) {
        te[j] = make_float2(time[j], expf(hazard[j]));
    }
    __syncthreads();

    const int lane = tid & 31;       // which i within the block
    const int p    = tid >> 5;       // j-partition (warp id)
    const int i    = blockIdx.x * I_PER_BLOCK + lane;
    const float ti = te[i].x;

    float acc = 0.0f;
    const int j0 = p * JCHUNK;
#pragma unroll 8
    for (int j = j0; j < j0 + JCHUNK; ++j) {
        float2 v = te[j];                    // broadcast across warp
        acc += (v.x >= ti) ? v.y : 0.0f;
    }

    // Reduce the 8 j-partitions per i: red[p*32 + lane]
    __shared__ float red[NTHREADS];
    red[tid] = acc;
    __syncthreads();
    if (tid < 128) red[tid] += red[tid + 128];
    __syncthreads();
    if (tid < 64)  red[tid] += red[tid + 64];
    __syncthreads();

    if (tid < 32) {
        float rs = red[tid] + red[tid + 32];          // full risk_sum[i]
        float c  = (hazard[i] - logf(rs)) * censor[i];
        // warp-reduce the 32 per-i contributions
#pragma unroll
        for (int o = 16; o > 0; o >>= 1)
            c += __shfl_down_sync(0xffffffffu, c, o);
        if (lane == 0) g_partials[blockIdx.x] = c;
    }
}

__global__ void __launch_bounds__(NTHREADS, 1)
cox_finalize_kernel(float* __restrict__ out)
{
    __shared__ float s[NTHREADS];
    const int tid = threadIdx.x;
    s[tid] = g_partials[tid];
    __syncthreads();
#pragma unroll
    for (int stride = NTHREADS / 2; stride >= 32; stride >>= 1) {
        if (tid < stride) s[tid] += s[tid + stride];
        __syncthreads();
    }
    if (tid < 32) {
        float v = s[tid];
#pragma unroll
        for (int o = 16; o > 0; o >>= 1)
            v += __shfl_down_sync(0xffffffffu, v, o);
        if (tid == 0) out[0] = -v / (float)N;
    }
}

extern "C" void kernel_launch(void* const* d_in, const int* in_sizes, int n_in,
                              void* d_out, int out_size)
{
    const float* hazard = (const float*)d_in[0];
    const float* time_  = (const float*)d_in[1];
    const float* censor = (const float*)d_in[2];
    float* out = (float*)d_out;

    const int smem = N * sizeof(float2);   // 64 KB
    static int attr_done = 0;
    if (!attr_done) {
        cudaFuncSetAttribute(cox_risk_kernel,
                             cudaFuncAttributeMaxDynamicSharedMemorySize, smem);
        attr_done = 1;
    }

    cox_risk_kernel<<<NBLOCKS, NTHREADS, smem>>>(hazard, time_, censor);
    cox_finalize_kernel<<<1, NTHREADS>>>(out);
}